// round 7
// baseline (speedup 1.0000x reference)
#include <cuda_runtime.h>
#include <cstdint>

// Problem constants
#define Bc 4
#define Nn 4096
#define Ff 64
#define ISPLIT 64         // i-range splits for colsum
#define TI 128            // i-rows per block in k_main
#define JC 64             // k-chunk (j columns) per stage
#define KSPLIT 2
#define CPB (Nn / JC / KSPLIT)   // 32 chunks per block
#define LOG2E 1.4426950408889634f
#define C08L  (0.8f * LOG2E)

// ---------------- scratch (device globals; no allocation allowed) ----------
__device__ float g_h   [Bc * Nn * Ff];      // h = inp @ W
__device__ float g_hsP [Bc * 64 * 4096];    // packed tf32 hs per chunk (seg layout)
__device__ float g_fsrc[Bc * Nn];           // 0.2*log2e * f_src (per i)
__device__ float g_fdst[Bc * Nn];           // 0.2*log2e * f_dst (per j)
__device__ float g_part[ISPLIT][Bc * Nn];   // colsum partials
__device__ float g_fbf [Bc * Nn];           // 1.0 if colsum==0 else 0.0
__device__ float g_pout[KSPLIT][Bc * Nn * Ff]; // k-split partial outputs

// ---------------- helpers ---------------------------------------------------
__device__ __forceinline__ float ex2f(float x) {
    float r; asm("ex2.approx.f32 %0, %1;" : "=f"(r) : "f"(x)); return r;
}
__device__ __forceinline__ uint32_t f2tf32(float x) {
    uint32_t u; asm("cvt.rna.tf32.f32 %0, %1;" : "=r"(u) : "f"(x)); return u;
}
__device__ __forceinline__ uint32_t smem_u32(const void* p) {
    uint32_t a;
    asm("{ .reg .u64 t; cvta.to.shared.u64 t, %1; cvt.u32.u64 %0, t; }" : "=r"(a) : "l"(p));
    return a;
}
__device__ __forceinline__ float4 ldcs4(const float* p) {
    float4 v;
    asm("ld.global.cs.v4.f32 {%0,%1,%2,%3}, [%4];"
        : "=f"(v.x), "=f"(v.y), "=f"(v.z), "=f"(v.w) : "l"(p));
    return v;
}
#define CPA16(dst, src) \
    asm volatile("cp.async.cg.shared.global [%0], [%1], 16;" :: "r"(dst), "l"(src))
#define MMA_TF32(c, a, b0, b1) \
    asm volatile("mma.sync.aligned.m16n8k8.row.col.f32.tf32.tf32.f32 " \
        "{%0,%1,%2,%3},{%4,%5,%6,%7},{%8,%9},{%0,%1,%2,%3};" \
        : "+f"((c)[0]), "+f"((c)[1]), "+f"((c)[2]), "+f"((c)[3]) \
        : "r"((a)[0]), "r"((a)[1]), "r"((a)[2]), "r"((a)[3]), "r"(b0), "r"(b1))

// hs ring: 3 stages x [hs 20480 | dj 256 | fb 256] = 3 x 20992
#define STAGE_SZ 20992u
#define SM_TOTAL (3u * STAGE_SZ)

// ============================================================================
// Kernel 1: h = inp @ W ; fsrc/fdst = 0.2*log2e * (lrelu(h) @ a halves)
// ============================================================================
__global__ __launch_bounds__(256) void k_prep(const float* __restrict__ inp,
                                              const float* __restrict__ W,
                                              const float* __restrict__ a) {
    __shared__ float Ws[64 * 64];
    __shared__ float as[128];
    __shared__ float inps[4][64];
    __shared__ float redS[4][2], redD[4][2];

    const int t = threadIdx.x;
    const int rowBase = blockIdx.x * 4;

    #pragma unroll
    for (int k = 0; k < 16; ++k) Ws[t + k * 256] = W[t + k * 256];
    if (t < 128) as[t] = a[t];

    const int r = t >> 6;
    const int o = t & 63;
    inps[r][o] = inp[(size_t)(rowBase + r) * 64 + o];
    __syncthreads();

    float hv = 0.f;
    #pragma unroll
    for (int f = 0; f < 64; ++f) hv = fmaf(inps[r][f], Ws[f * 64 + o], hv);

    const int gRow = rowBase + r;
    g_h[(size_t)gRow * 64 + o] = hv;

    const float lh = hv > 0.f ? hv : 0.2f * hv;
    float ps = lh * as[o];
    float pd = lh * as[64 + o];
    #pragma unroll
    for (int off = 16; off > 0; off >>= 1) {
        ps += __shfl_xor_sync(0xffffffffu, ps, off);
        pd += __shfl_xor_sync(0xffffffffu, pd, off);
    }
    const int wh = (t >> 5) & 1;
    if ((t & 31) == 0) { redS[r][wh] = ps; redD[r][wh] = pd; }
    __syncthreads();
    if ((t & 63) == 0) {
        g_fsrc[gRow] = 0.2f * LOG2E * (redS[r][0] + redS[r][1]);
        g_fdst[gRow] = 0.2f * LOG2E * (redD[r][0] + redD[r][1]);
    }
}

// ============================================================================
// Kernel 2: colsum partials. p_ij = (t>0 ? 2^t : 0). grid (4, 64, 4).
// ============================================================================
__global__ __launch_bounds__(256) void k_colsum(const float* __restrict__ adj) {
    const int b  = blockIdx.z;
    const int j  = (blockIdx.x * 256 + threadIdx.x) * 4;
    const int i0 = blockIdx.y * (Nn / ISPLIT);
    const float4 dj = *(const float4*)(g_fdst + b * Nn + j);
    const float* __restrict__ fs = g_fsrc + b * Nn + i0;
    const float* __restrict__ ap = adj + ((size_t)b * Nn + i0) * Nn + j;

    float4 sum = make_float4(0.f, 0.f, 0.f, 0.f);
    #pragma unroll 16
    for (int i = 0; i < Nn / ISPLIT; ++i) {
        const float ci = fs[i];
        const float4 a = ldcs4(ap + (size_t)i * Nn);
        const float t0 = fmaf(C08L, a.x, ci + dj.x);
        const float t1 = fmaf(C08L, a.y, ci + dj.y);
        const float t2 = fmaf(C08L, a.z, ci + dj.z);
        const float t3 = fmaf(C08L, a.w, ci + dj.w);
        sum.x += (t0 > 0.f) ? ex2f(t0) : 0.f;
        sum.y += (t1 > 0.f) ? ex2f(t1) : 0.f;
        sum.z += (t2 > 0.f) ? ex2f(t2) : 0.f;
        sum.w += (t3 > 0.f) ? ex2f(t3) : 0.f;
    }
    *(float4*)(&g_part[blockIdx.y][b * Nn + j]) = sum;
}

// ============================================================================
// Kernel 3: reduce partials; pack hs (tf32) into B-fragment layout with the
// PERMUTED k mapping: fragment slot (k3, half) -> actual j offset 2*k3 + half.
// ============================================================================
__global__ __launch_bounds__(256) void k_hpack() {
    __shared__ float sc[64];
    __shared__ float qsum[4][64];
    const int t = threadIdx.x;
    const int c = blockIdx.x;
    const int b = blockIdx.y;
    const int j0 = c * 64;

    {
        const int jl = t & 63;
        const int sq = t >> 6;
        float cs = 0.f;
        #pragma unroll
        for (int s = 0; s < ISPLIT / 4; ++s)
            cs += g_part[sq * (ISPLIT / 4) + s][b * Nn + j0 + jl];
        qsum[sq][jl] = cs;
    }
    __syncthreads();
    if (t < 64) {
        const float cs = qsum[0][t] + qsum[1][t] + qsum[2][t] + qsum[3][t];
        sc[t] = cs > 0.f ? (1.f / cs) : (1.f / (float)Nn);
        g_fbf[b * Nn + j0 + t] = cs > 0.f ? 0.f : 1.f;
    }
    __syncthreads();

    float* __restrict__ dst = g_hsP + (size_t)(b * 64 + c) * 4096;
    #pragma unroll
    for (int r = 0; r < 16; ++r) {
        const int o = t + r * 256;
        const int s = o >> 4, i = o & 15;
        const int ks = s >> 5, n07 = (s >> 2) & 7, k3 = s & 3;
        const int nt = i >> 1, half = i & 1;
        const int jl = ks * 8 + 2 * k3 + half;   // permuted k mapping
        const int f  = nt * 8 + n07;
        const float v = g_h[((size_t)(b * Nn) + j0 + jl) * 64 + f] * sc[jl];
        dst[o] = __uint_as_float(f2tf32(v));
    }
}

// ============================================================================
// Kernel 4 (hot): partial out = A_att @ hs via mma.sync tf32.
// adj: direct coalesced LDG.64 -> registers -> exp -> A fragments (NO smem).
// hs:  3-deep cp.async ring in smem (20.5KB/stage). One barrier per chunk.
// TI=128, 256 thr = 8 warps x 16 rows. grid (32, Bc, 2). 2 CTAs/SM.
// ============================================================================
__device__ __forceinline__ void issue_hs(uint32_t sm, int stage,
                                         const float* __restrict__ hsPb,
                                         const float* __restrict__ djB,
                                         const float* __restrict__ fbB,
                                         int cglob, int t) {
    const uint32_t base = sm + (uint32_t)stage * STAGE_SZ;
    const float* __restrict__ hsrc = hsPb + (size_t)cglob * 4096;
    #pragma unroll
    for (int q = 0; q < 4; ++q) {
        const int quad = t + q * 256;
        const int s = quad >> 2, v = quad & 3;
        CPA16(base + (uint32_t)s * 80u + (uint32_t)v * 16u, hsrc + quad * 4);
    }
    const int j0 = cglob * JC;
    if (t < 16)
        CPA16(base + 20480u + (uint32_t)t * 16u, djB + j0 + t * 4);
    else if (t < 32)
        CPA16(base + 20736u + (uint32_t)(t - 16) * 16u, fbB + j0 + (t - 16) * 4);
}

__global__ __launch_bounds__(256, 2) void k_main(const float* __restrict__ adj) {
    extern __shared__ char dsm[];
    const uint32_t sm = smem_u32(dsm);

    const int t    = threadIdx.x;
    const int wid  = t >> 5;      // warp owns rows wid*16 .. wid*16+15
    const int lane = t & 31;
    const int lq   = lane >> 2;
    const int lm   = lane & 3;
    const int b    = blockIdx.y;
    const int i0   = blockIdx.x * TI;
    const int ks   = blockIdx.z;
    const int c0g  = ks * CPB;

    const float* __restrict__ hsPb = g_hsP + (size_t)b * 64 * 4096;
    const float* __restrict__ djB  = g_fdst + b * Nn;
    const float* __restrict__ fbB  = g_fbf  + b * Nn;

    // per-thread adj row pointers (permuted-k: cols 2*lm, 2*lm+1 per kk group)
    const float* __restrict__ pr0 =
        adj + ((size_t)b * Nn + i0 + wid * 16 + lq) * Nn + c0g * JC + 2 * lm;
    const float* __restrict__ pr1 = pr0 + (size_t)8 * Nn;

    float cil[2];
    #pragma unroll
    for (int sel = 0; sel < 2; ++sel)
        cil[sel] = g_fsrc[b * Nn + i0 + wid * 16 + sel * 8 + lq];

    float acc[8][4];
    #pragma unroll
    for (int nt = 0; nt < 8; ++nt)
        #pragma unroll
        for (int q = 0; q < 4; ++q) acc[nt][q] = 0.f;

    // prologue: hs stages 0,1 in flight
    issue_hs(sm, 0, hsPb, djB, fbB, c0g + 0, t);
    asm volatile("cp.async.commit_group;" ::: "memory");
    issue_hs(sm, 1, hsPb, djB, fbB, c0g + 1, t);
    asm volatile("cp.async.commit_group;" ::: "memory");

    // prologue: adj batch A (kk 0..3 of chunk 0)
    float2 aA[8], aB[8];
    #pragma unroll
    for (int kk = 0; kk < 4; ++kk) {
        aA[kk * 2 + 0] = *(const float2*)(pr0 + kk * 8);
        aA[kk * 2 + 1] = *(const float2*)(pr1 + kk * 8);
    }

    for (int c = 0; c < CPB; ++c) {
        asm volatile("cp.async.wait_group 1;" ::: "memory");
        __syncthreads();   // hs[c] visible; all warps done reading stage (c-1)%3
        if (c + 2 < CPB)
            issue_hs(sm, (c + 2) % 3, hsPb, djB, fbB, c0g + c + 2, t);
        asm volatile("cp.async.commit_group;" ::: "memory");

        // adj batch B (kk 4..7 of chunk c)
        #pragma unroll
        for (int kk = 0; kk < 4; ++kk) {
            aB[kk * 2 + 0] = *(const float2*)(pr0 + c * JC + 32 + kk * 8);
            aB[kk * 2 + 1] = *(const float2*)(pr1 + c * JC + 32 + kk * 8);
        }

        const uint32_t stg = sm + (uint32_t)(c % 3) * STAGE_SZ;
        const float* djS = (const float*)(dsm + (c % 3) * STAGE_SZ + 20480);
        const float* fbS = (const float*)(dsm + (c % 3) * STAGE_SZ + 20736);

        #pragma unroll
        for (int half = 0; half < 2; ++half) {
            const float2* aX = half ? aB : aA;
            #pragma unroll
            for (int k4 = 0; k4 < 4; ++k4) {
                const int kk = half * 4 + k4;
                const float2 djv = *(const float2*)(djS + kk * 8 + 2 * lm);
                const float2 fbv = *(const float2*)(fbS + kk * 8 + 2 * lm);
                const float2 a0 = aX[k4 * 2 + 0];
                const float2 a1 = aX[k4 * 2 + 1];

                const float t00 = fmaf(C08L, a0.x, cil[0] + djv.x);
                const float t10 = fmaf(C08L, a1.x, cil[1] + djv.x);
                const float t01 = fmaf(C08L, a0.y, cil[0] + djv.y);
                const float t11 = fmaf(C08L, a1.y, cil[1] + djv.y);

                uint32_t au[4];
                au[0] = f2tf32(t00 > 0.f ? ex2f(t00) : fbv.x);
                au[1] = f2tf32(t10 > 0.f ? ex2f(t10) : fbv.x);
                au[2] = f2tf32(t01 > 0.f ? ex2f(t01) : fbv.y);
                au[3] = f2tf32(t11 > 0.f ? ex2f(t11) : fbv.y);

                // B fragments: 4 x LDS.128, seg = kk*32 + lane
                uint32_t bfr[16];
                #pragma unroll
                for (int v = 0; v < 4; ++v) {
                    const uint32_t ba = stg + (uint32_t)(kk * 32 + lane) * 80u
                                      + (uint32_t)v * 16u;
                    asm volatile("ld.shared.v4.b32 {%0,%1,%2,%3}, [%4];"
                                 : "=r"(bfr[v * 4]), "=r"(bfr[v * 4 + 1]),
                                   "=r"(bfr[v * 4 + 2]), "=r"(bfr[v * 4 + 3])
                                 : "r"(ba));
                }
                #pragma unroll
                for (int nt = 0; nt < 8; ++nt) {
                    const uint32_t b0 = bfr[(nt >> 1) * 4 + (nt & 1) * 2];
                    const uint32_t b1 = bfr[(nt >> 1) * 4 + (nt & 1) * 2 + 1];
                    MMA_TF32(acc[nt], au, b0, b1);
                }
            }
            // after consuming batch A, prefetch batch A of chunk c+1
            if (half == 0 && c + 1 < CPB) {
                #pragma unroll
                for (int kk = 0; kk < 4; ++kk) {
                    aA[kk * 2 + 0] = *(const float2*)(pr0 + (c + 1) * JC + kk * 8);
                    aA[kk * 2 + 1] = *(const float2*)(pr1 + (c + 1) * JC + kk * 8);
                }
            }
        }
    }

    // epilogue: partial store
    float* __restrict__ pout = g_pout[ks] + ((size_t)(b * Nn) + i0 + wid * 16) * 64;
    #pragma unroll
    for (int nt = 0; nt < 8; ++nt) {
        const size_t base = (size_t)lq * 64 + nt * 8 + 2 * lm;
        *(float2*)(pout + base)          = make_float2(acc[nt][0], acc[nt][1]);
        *(float2*)(pout + base + 8 * 64) = make_float2(acc[nt][2], acc[nt][3]);
    }
}

// ============================================================================
// Kernel 5: out = relu(p0 + p1)
// ============================================================================
__global__ __launch_bounds__(256) void k_fin(float* __restrict__ out) {
    const int idx = (blockIdx.x * 256 + threadIdx.x) * 4;
    const float4 p0 = *(const float4*)(&g_pout[0][idx]);
    const float4 p1 = *(const float4*)(&g_pout[1][idx]);
    float4 r;
    r.x = fmaxf(p0.x + p1.x, 0.f);
    r.y = fmaxf(p0.y + p1.y, 0.f);
    r.z = fmaxf(p0.z + p1.z, 0.f);
    r.w = fmaxf(p0.w + p1.w, 0.f);
    *(float4*)(out + idx) = r;
}

// ============================================================================
extern "C" void kernel_launch(void* const* d_in, const int* in_sizes, int n_in,
                              void* d_out, int out_size) {
    const float *inp = nullptr, *adj = nullptr, *W = nullptr, *a = nullptr;
    for (int i = 0; i < n_in; ++i) {
        switch (in_sizes[i]) {
            case 1048576:  inp = (const float*)d_in[i]; break; // 4*4096*64
            case 67108864: adj = (const float*)d_in[i]; break; // 4*4096*4096
            case 4096:     W   = (const float*)d_in[i]; break; // 64*64
            case 128:      a   = (const float*)d_in[i]; break; // 128*1
            default: break;
        }
    }
    float* out = (float*)d_out;

    cudaFuncSetAttribute(k_main, cudaFuncAttributeMaxDynamicSharedMemorySize, SM_TOTAL);

    k_prep<<<Bc * Nn / 4, 256>>>(inp, W, a);

    dim3 g2(Nn / 1024, ISPLIT, Bc);
    k_colsum<<<g2, 256>>>(adj);

    dim3 g3(64, Bc);
    k_hpack<<<g3, 256>>>();

    dim3 g4(Nn / TI, Bc, KSPLIT);
    k_main<<<g4, 256, SM_TOTAL>>>(adj);

    k_fin<<<Bc * Nn * Ff / 1024, 256>>>(out);
}

// round 8
// speedup vs baseline: 1.0019x; 1.0019x over previous
#include <cuda_runtime.h>
#include <cstdint>

// Problem constants
#define Bc 4
#define Nn 4096
#define Ff 64
#define TI 128            // i-rows per block in k_main
#define KSPLIT 2
#define NH 64             // half-chunks (32 j each) per CTA
#define LOG2E 1.4426950408889634f
#define C08L  (0.8f * LOG2E)
#define NPART 128         // i-blocks in k_csum (32 rows each)

// ---------------- scratch (device globals; no allocation allowed) ----------
__device__ float g_h   [Bc * Nn * Ff];       // h = inp @ W
__device__ float g_hsC [Bc * 64 * 5120];     // per-chunk blob: 2 half-blobs x 128 segs x 20 floats
__device__ float g_fsrc[Bc * Nn];            // 0.2*log2e * f_src (per i)
__device__ float g_fdst[Bc * Nn];            // 0.2*log2e * f_dst (per j)
__device__ float g_part[NPART][Bc * Nn];     // colsum partials (per i-block)
__device__ float g_pout[KSPLIT][Bc * Nn * Ff]; // k-split partial outputs

// ---------------- helpers ---------------------------------------------------
__device__ __forceinline__ float ex2f(float x) {
    float r; asm("ex2.approx.f32 %0, %1;" : "=f"(r) : "f"(x)); return r;
}
__device__ __forceinline__ uint32_t f2tf32(float x) {
    uint32_t u; asm("cvt.rna.tf32.f32 %0, %1;" : "=r"(u) : "f"(x)); return u;
}
__device__ __forceinline__ uint32_t smem_u32(const void* p) {
    uint32_t a;
    asm("{ .reg .u64 t; cvta.to.shared.u64 t, %1; cvt.u32.u64 %0, t; }" : "=r"(a) : "l"(p));
    return a;
}
__device__ __forceinline__ float4 ldcs4(const float* p) {
    float4 v;
    asm("ld.global.cs.v4.f32 {%0,%1,%2,%3}, [%4];"
        : "=f"(v.x), "=f"(v.y), "=f"(v.z), "=f"(v.w) : "l"(p));
    return v;
}
#define CPA16(dst, src) \
    asm volatile("cp.async.cg.shared.global [%0], [%1], 16;" :: "r"(dst), "l"(src))
#define MMA_TF32(c, a, b0, b1) \
    asm volatile("mma.sync.aligned.m16n8k8.row.col.f32.tf32.tf32.f32 " \
        "{%0,%1,%2,%3},{%4,%5,%6,%7},{%8,%9},{%0,%1,%2,%3};" \
        : "+f"((c)[0]), "+f"((c)[1]), "+f"((c)[2]), "+f"((c)[3]) \
        : "r"((a)[0]), "r"((a)[1]), "r"((a)[2]), "r"((a)[3]), "r"(b0), "r"(b1))

// k_main smem: 4 half-stages of [adj 128x36 floats | hs-blob 128 segs x 80B]
#define ADJ_ROW_B 144u                 // 36 floats per adj row (conflict-free LDS)
#define ST_ADJ    18432u               // 128 * 144
#define ST_HS     10240u               // 128 segs * 80B (incl dj/fb in seg pad)
#define STAGE     (ST_ADJ + ST_HS)     // 28672
#define SM_TOTAL  (4u * STAGE)         // 114688 -> 2 CTAs/SM

// ============================================================================
// Kernel 1: h = inp @ W ; fsrc/fdst = 0.2*log2e * (lrelu(h) @ a halves)
// ============================================================================
__global__ __launch_bounds__(256) void k_prep(const float* __restrict__ inp,
                                              const float* __restrict__ W,
                                              const float* __restrict__ a) {
    __shared__ float Ws[64 * 64];
    __shared__ float as[128];
    __shared__ float inps[4][64];
    __shared__ float redS[4][2], redD[4][2];

    const int t = threadIdx.x;
    const int rowBase = blockIdx.x * 4;

    #pragma unroll
    for (int k = 0; k < 16; ++k) Ws[t + k * 256] = W[t + k * 256];
    if (t < 128) as[t] = a[t];

    const int r = t >> 6;
    const int o = t & 63;
    inps[r][o] = inp[(size_t)(rowBase + r) * 64 + o];
    __syncthreads();

    float hv = 0.f;
    #pragma unroll
    for (int f = 0; f < 64; ++f) hv = fmaf(inps[r][f], Ws[f * 64 + o], hv);

    const int gRow = rowBase + r;
    g_h[(size_t)gRow * 64 + o] = hv;

    const float lh = hv > 0.f ? hv : 0.2f * hv;
    float ps = lh * as[o];
    float pd = lh * as[64 + o];
    #pragma unroll
    for (int off = 16; off > 0; off >>= 1) {
        ps += __shfl_xor_sync(0xffffffffu, ps, off);
        pd += __shfl_xor_sync(0xffffffffu, pd, off);
    }
    const int wh = (t >> 5) & 1;
    if ((t & 31) == 0) { redS[r][wh] = ps; redD[r][wh] = pd; }
    __syncthreads();
    if ((t & 63) == 0) {
        g_fsrc[gRow] = 0.2f * LOG2E * (redS[r][0] + redS[r][1]);
        g_fdst[gRow] = 0.2f * LOG2E * (redD[r][0] + redD[r][1]);
    }
}

// ============================================================================
// Kernel 2 (k_csum): colsum partials with SEQUENTIAL row streaming.
// grid (128, Bc), 256 thr. CTA owns 32 consecutive i-rows x ALL 4096 j.
// Thread keeps 16 register sums at fixed j = k*1024 + t*4 + e.
// ============================================================================
__global__ __launch_bounds__(256) void k_csum(const float* __restrict__ adj) {
    const int b   = blockIdx.y;
    const int blk = blockIdx.x;          // i-block 0..127
    const int t   = threadIdx.x;

    const float* __restrict__ ap = adj + ((size_t)b * Nn + blk * 32) * Nn + t * 4;
    const float* __restrict__ fs = g_fsrc + b * Nn + blk * 32;

    float4 dj[4], s[4];
    #pragma unroll
    for (int k = 0; k < 4; ++k) {
        dj[k] = *(const float4*)(g_fdst + b * Nn + k * 1024 + t * 4);
        s[k] = make_float4(0.f, 0.f, 0.f, 0.f);
    }

    #pragma unroll 2
    for (int r = 0; r < 32; ++r) {
        const float ci = fs[r];
        float4 a[4];
        #pragma unroll
        for (int k = 0; k < 4; ++k) a[k] = ldcs4(ap + (size_t)r * Nn + k * 1024);
        #pragma unroll
        for (int k = 0; k < 4; ++k) {
            const float t0 = fmaf(C08L, a[k].x, ci + dj[k].x);
            const float t1 = fmaf(C08L, a[k].y, ci + dj[k].y);
            const float t2 = fmaf(C08L, a[k].z, ci + dj[k].z);
            const float t3 = fmaf(C08L, a[k].w, ci + dj[k].w);
            s[k].x += (t0 > 0.f) ? ex2f(t0) : 0.f;
            s[k].y += (t1 > 0.f) ? ex2f(t1) : 0.f;
            s[k].z += (t2 > 0.f) ? ex2f(t2) : 0.f;
            s[k].w += (t3 > 0.f) ? ex2f(t3) : 0.f;
        }
    }
    #pragma unroll
    for (int k = 0; k < 4; ++k)
        *(float4*)(&g_part[blk][b * Nn + k * 1024 + t * 4]) = s[k];
}

// ============================================================================
// Kernel 3: reduce 128 partials; pack hs (tf32) + dj/fb pads into blobs.
// grid (64, Bc), 256 thr. Blob per chunk: 2 half-blobs x 128 segs x 20 floats;
// seg pad floats [16],[17] carry dj, fb for local j' = seg index (segs 0..31).
// ============================================================================
__global__ __launch_bounds__(256) void k_hpack() {
    __shared__ float sc[64];
    __shared__ float qsum[4][64];
    const int t = threadIdx.x;
    const int c = blockIdx.x;
    const int b = blockIdx.y;
    const int j0 = c * 64;

    {
        const int jl = t & 63;
        const int sl = t >> 6;           // slice 0..3 of 32 partials each
        float cs = 0.f;
        #pragma unroll
        for (int s = 0; s < 32; ++s)
            cs += g_part[sl * 32 + s][b * Nn + j0 + jl];
        qsum[sl][jl] = cs;
    }
    __syncthreads();

    float* __restrict__ dst = g_hsC + (size_t)(b * 64 + c) * 5120;

    if (t < 64) {
        const float cs = qsum[0][t] + qsum[1][t] + qsum[2][t] + qsum[3][t];
        sc[t] = cs > 0.f ? (1.f / cs) : (1.f / (float)Nn);
        // dj/fb pads: half = t>>5, local j' = t&31 -> seg j' of that half-blob
        const int off = (t >> 5) * 2560 + (t & 31) * 20;
        dst[off + 16] = g_fdst[b * Nn + j0 + t];
        dst[off + 17] = cs > 0.f ? 0.f : 1.f;
    }
    __syncthreads();

    #pragma unroll
    for (int r = 0; r < 16; ++r) {
        const int o = t + r * 256;              // 0..4095
        const int s = o >> 4, i = o & 15;       // global seg 0..255
        const int ks = s >> 5;                  // kk group 0..7
        const int n07 = (s >> 2) & 7, k3 = s & 3;
        const int nt = i >> 1, h2 = i & 1;
        const int jl = ks * 8 + k3 + 4 * h2;    // j within chunk
        const int f  = nt * 8 + n07;
        const int halfidx = ks >> 2, kkloc = ks & 3;
        const float v = g_h[((size_t)(b * Nn) + j0 + jl) * 64 + f] * sc[jl];
        dst[halfidx * 2560 + (kkloc * 32 + (s & 31)) * 20 + i] =
            __uint_as_float(f2tf32(v));
    }
}

// ============================================================================
// Kernel 4 (hot): partial out = A_att @ hs via mma.sync tf32.
// 4-deep half-chunk pipeline, ONE barrier per half. TI=128, 8 warps x 16 rows.
// grid (32, Bc, 2), 2 CTAs/SM.
// ============================================================================
__device__ __forceinline__ void issue_half(uint32_t stg,
                                           const float* __restrict__ adjB,
                                           const float* __restrict__ hsCb,
                                           int hglob, int t) {
    // adj half tile: 128 rows x 32 cols, row stride 144B
    const float* __restrict__ asrc = adjB + hglob * 32;
    #pragma unroll
    for (int q = 0; q < 4; ++q) {
        const int quad = t + q * 256;           // 0..1023
        const int row = quad >> 3, c4 = quad & 7;
        CPA16(stg + (uint32_t)row * ADJ_ROW_B + (uint32_t)c4 * 16u,
              asrc + (size_t)row * Nn + c4 * 4);
    }
    // hs half blob: flat 2560 floats = 640 quads
    const float* __restrict__ hsrc = hsCb + (size_t)hglob * 2560;
    const uint32_t hb = stg + ST_ADJ;
    CPA16(hb + (uint32_t)t * 16u, hsrc + t * 4);
    CPA16(hb + (uint32_t)(t + 256) * 16u, hsrc + (t + 256) * 4);
    if (t < 128)
        CPA16(hb + (uint32_t)(t + 512) * 16u, hsrc + (t + 512) * 4);
}

__global__ __launch_bounds__(256, 2) void k_main(const float* __restrict__ adj) {
    extern __shared__ char dsm[];
    const uint32_t sm = smem_u32(dsm);

    const int t    = threadIdx.x;
    const int wid  = t >> 5;      // warp owns rows wid*16 .. wid*16+15
    const int lane = t & 31;
    const int lq   = lane >> 2;
    const int lm   = lane & 3;
    const int b    = blockIdx.y;
    const int i0   = blockIdx.x * TI;
    const int ks   = blockIdx.z;
    const int h0   = ks * NH;     // first global half index

    const float* __restrict__ adjB = adj + ((size_t)b * Nn + i0) * Nn;
    const float* __restrict__ hsCb = g_hsC + (size_t)b * 64 * 5120;

    float cil[2];
    #pragma unroll
    for (int sel = 0; sel < 2; ++sel)
        cil[sel] = g_fsrc[b * Nn + i0 + wid * 16 + sel * 8 + lq];

    float acc[8][4];
    #pragma unroll
    for (int nt = 0; nt < 8; ++nt)
        #pragma unroll
        for (int q = 0; q < 4; ++q) acc[nt][q] = 0.f;

    // prologue: halves 0,1,2 in flight
    #pragma unroll
    for (int p = 0; p < 3; ++p) {
        issue_half(sm + (uint32_t)p * STAGE, adjB, hsCb, h0 + p, t);
        asm volatile("cp.async.commit_group;" ::: "memory");
    }

    for (int h = 0; h < NH; ++h) {
        asm volatile("cp.async.wait_group 2;" ::: "memory");
        __syncthreads();   // data[h] visible; all warps done with stage (h-1)&3
        if (h + 3 < NH)
            issue_half(sm + (uint32_t)((h + 3) & 3) * STAGE, adjB, hsCb,
                       h0 + h + 3, t);
        asm volatile("cp.async.commit_group;" ::: "memory");

        const uint32_t stg  = sm + (uint32_t)(h & 3) * STAGE;
        const uint32_t hsb  = stg + ST_ADJ;
        const uint32_t adjW = stg + (uint32_t)(wid * 16) * ADJ_ROW_B;

        #pragma unroll
        for (int kkloc = 0; kkloc < 4; ++kkloc) {
            float dj0, fb0, dj4, fb4;
            {
                const uint32_t p0 = hsb + (uint32_t)(kkloc * 8 + lm) * 80u + 64u;
                const uint32_t p4 = hsb + (uint32_t)(kkloc * 8 + lm + 4) * 80u + 64u;
                asm volatile("ld.shared.v2.f32 {%0,%1}, [%2];"
                             : "=f"(dj0), "=f"(fb0) : "r"(p0));
                asm volatile("ld.shared.v2.f32 {%0,%1}, [%2];"
                             : "=f"(dj4), "=f"(fb4) : "r"(p4));
            }
            // B fragments: 4 x LDS.128, seg = kkloc*32 + lane
            uint32_t bfr[16];
            #pragma unroll
            for (int v = 0; v < 4; ++v) {
                const uint32_t ba = hsb + (uint32_t)(kkloc * 32 + lane) * 80u
                                  + (uint32_t)v * 16u;
                asm volatile("ld.shared.v4.b32 {%0,%1,%2,%3}, [%4];"
                             : "=r"(bfr[v * 4]), "=r"(bfr[v * 4 + 1]),
                               "=r"(bfr[v * 4 + 2]), "=r"(bfr[v * 4 + 3])
                             : "r"(ba));
            }
            // A fragment
            uint32_t au[4];
            #pragma unroll
            for (int kh = 0; kh < 2; ++kh) {
                const float djv = kh ? dj4 : dj0;
                const float fbv = kh ? fb4 : fb0;
                #pragma unroll
                for (int sel = 0; sel < 2; ++sel) {
                    float av;
                    const uint32_t aa = adjW
                        + (uint32_t)(sel * 8 + lq) * ADJ_ROW_B
                        + (uint32_t)(kkloc * 8 + lm + 4 * kh) * 4u;
                    asm volatile("ld.shared.f32 %0, [%1];" : "=f"(av) : "r"(aa));
                    const float tl = fmaf(C08L, av, cil[sel] + djv);
                    const float w  = tl > 0.f ? ex2f(tl) : fbv;
                    au[sel + 2 * kh] = f2tf32(w);
                }
            }
            #pragma unroll
            for (int nt = 0; nt < 8; ++nt) {
                const uint32_t b0 = bfr[(nt >> 1) * 4 + (nt & 1) * 2];
                const uint32_t b1 = bfr[(nt >> 1) * 4 + (nt & 1) * 2 + 1];
                MMA_TF32(acc[nt], au, b0, b1);
            }
        }
    }

    // epilogue: partial store
    float* __restrict__ pout = g_pout[ks] + ((size_t)(b * Nn) + i0 + wid * 16) * 64;
    #pragma unroll
    for (int nt = 0; nt < 8; ++nt) {
        const size_t base = (size_t)lq * 64 + nt * 8 + 2 * lm;
        *(float2*)(pout + base)          = make_float2(acc[nt][0], acc[nt][1]);
        *(float2*)(pout + base + 8 * 64) = make_float2(acc[nt][2], acc[nt][3]);
    }
}

// ============================================================================
// Kernel 5: out = relu(p0 + p1)
// ============================================================================
__global__ __launch_bounds__(256) void k_fin(float* __restrict__ out) {
    const int idx = (blockIdx.x * 256 + threadIdx.x) * 4;
    const float4 p0 = *(const float4*)(&g_pout[0][idx]);
    const float4 p1 = *(const float4*)(&g_pout[1][idx]);
    float4 r;
    r.x = fmaxf(p0.x + p1.x, 0.f);
    r.y = fmaxf(p0.y + p1.y, 0.f);
    r.z = fmaxf(p0.z + p1.z, 0.f);
    r.w = fmaxf(p0.w + p1.w, 0.f);
    *(float4*)(out + idx) = r;
}

// ============================================================================
extern "C" void kernel_launch(void* const* d_in, const int* in_sizes, int n_in,
                              void* d_out, int out_size) {
    const float *inp = nullptr, *adj = nullptr, *W = nullptr, *a = nullptr;
    for (int i = 0; i < n_in; ++i) {
        switch (in_sizes[i]) {
            case 1048576:  inp = (const float*)d_in[i]; break; // 4*4096*64
            case 67108864: adj = (const float*)d_in[i]; break; // 4*4096*4096
            case 4096:     W   = (const float*)d_in[i]; break; // 64*64
            case 128:      a   = (const float*)d_in[i]; break; // 128*1
            default: break;
        }
    }
    float* out = (float*)d_out;

    cudaFuncSetAttribute(k_main, cudaFuncAttributeMaxDynamicSharedMemorySize, SM_TOTAL);

    k_prep<<<Bc * Nn / 4, 256>>>(inp, W, a);

    dim3 g2(NPART, Bc);
    k_csum<<<g2, 256>>>(adj);

    dim3 g3(64, Bc);
    k_hpack<<<g3, 256>>>();

    dim3 g4(Nn / TI, Bc, KSPLIT);
    k_main<<<g4, 256, SM_TOTAL>>>(adj);

    k_fin<<<Bc * Nn * Ff / 1024, 256>>>(out);
}

// round 9
// speedup vs baseline: 1.1072x; 1.1050x over previous
#include <cuda_runtime.h>
#include <cstdint>

// Problem constants
#define Bc 4
#define Nn 4096
#define Ff 64
#define ISPLIT 64         // i-range splits for colsum
#define TI 128            // i-rows per block in k_main
#define KSPLIT 2
#define NH 64             // half-chunks (32 j each) per CTA
#define LOG2E 1.4426950408889634f
#define C08L  (0.8f * LOG2E)

// ---------------- scratch (device globals; no allocation allowed) ----------
__device__ float g_h   [Bc * Nn * Ff];       // h = inp @ W
__device__ float g_hsC [Bc * 64 * 5120];     // per-chunk blob: 2 half-blobs x 128 segs x 20 floats
__device__ float g_fsrc[Bc * Nn];            // 0.2*log2e * f_src (per i)
__device__ float g_fdst[Bc * Nn];            // 0.2*log2e * f_dst (per j)
__device__ float g_part[ISPLIT][Bc * Nn];    // colsum partials
__device__ float g_pout[KSPLIT][Bc * Nn * Ff]; // k-split partial outputs

// ---------------- helpers ---------------------------------------------------
__device__ __forceinline__ float ex2f(float x) {
    float r; asm("ex2.approx.f32 %0, %1;" : "=f"(r) : "f"(x)); return r;
}
__device__ __forceinline__ uint32_t f2tf32(float x) {
    uint32_t u; asm("cvt.rna.tf32.f32 %0, %1;" : "=r"(u) : "f"(x)); return u;
}
__device__ __forceinline__ uint32_t smem_u32(const void* p) {
    uint32_t a;
    asm("{ .reg .u64 t; cvta.to.shared.u64 t, %1; cvt.u32.u64 %0, t; }" : "=r"(a) : "l"(p));
    return a;
}
__device__ __forceinline__ float4 ldcs4(const float* p) {
    float4 v;
    asm("ld.global.cs.v4.f32 {%0,%1,%2,%3}, [%4];"
        : "=f"(v.x), "=f"(v.y), "=f"(v.z), "=f"(v.w) : "l"(p));
    return v;
}
#define CPA16(dst, src) \
    asm volatile("cp.async.cg.shared.global [%0], [%1], 16;" :: "r"(dst), "l"(src))
#define MMA_TF32(c, a, b0, b1) \
    asm volatile("mma.sync.aligned.m16n8k8.row.col.f32.tf32.tf32.f32 " \
        "{%0,%1,%2,%3},{%4,%5,%6,%7},{%8,%9},{%0,%1,%2,%3};" \
        : "+f"((c)[0]), "+f"((c)[1]), "+f"((c)[2]), "+f"((c)[3]) \
        : "r"((a)[0]), "r"((a)[1]), "r"((a)[2]), "r"((a)[3]), "r"(b0), "r"(b1))

// k_main smem: 4 half-stages of [adj 128x36 floats | hs-blob 128 segs x 80B]
#define ADJ_ROW_B 144u                 // 36 floats per adj row (conflict-free LDS)
#define ST_ADJ    18432u               // 128 * 144
#define ST_HS     10240u               // 128 segs * 80B (incl dj/fb in seg pad)
#define STAGE     (ST_ADJ + ST_HS)     // 28672
#define SM_TOTAL  (4u * STAGE)         // 114688 -> 2 CTAs/SM

// ============================================================================
// Kernel 1: h = inp @ W ; fsrc/fdst = 0.2*log2e * (lrelu(h) @ a halves)
// ============================================================================
__global__ __launch_bounds__(256) void k_prep(const float* __restrict__ inp,
                                              const float* __restrict__ W,
                                              const float* __restrict__ a) {
    __shared__ float Ws[64 * 64];
    __shared__ float as[128];
    __shared__ float inps[4][64];
    __shared__ float redS[4][2], redD[4][2];

    const int t = threadIdx.x;
    const int rowBase = blockIdx.x * 4;

    #pragma unroll
    for (int k = 0; k < 16; ++k) Ws[t + k * 256] = W[t + k * 256];
    if (t < 128) as[t] = a[t];

    const int r = t >> 6;
    const int o = t & 63;
    inps[r][o] = inp[(size_t)(rowBase + r) * 64 + o];
    __syncthreads();

    float hv = 0.f;
    #pragma unroll
    for (int f = 0; f < 64; ++f) hv = fmaf(inps[r][f], Ws[f * 64 + o], hv);

    const int gRow = rowBase + r;
    g_h[(size_t)gRow * 64 + o] = hv;

    const float lh = hv > 0.f ? hv : 0.2f * hv;
    float ps = lh * as[o];
    float pd = lh * as[64 + o];
    #pragma unroll
    for (int off = 16; off > 0; off >>= 1) {
        ps += __shfl_xor_sync(0xffffffffu, ps, off);
        pd += __shfl_xor_sync(0xffffffffu, pd, off);
    }
    const int wh = (t >> 5) & 1;
    if ((t & 31) == 0) { redS[r][wh] = ps; redD[r][wh] = pd; }
    __syncthreads();
    if ((t & 63) == 0) {
        g_fsrc[gRow] = 0.2f * LOG2E * (redS[r][0] + redS[r][1]);
        g_fdst[gRow] = 0.2f * LOG2E * (redD[r][0] + redD[r][1]);
    }
}

// ============================================================================
// Kernel 2: colsum partials (R6 form — measured best). grid (4, 64, 4).
// ============================================================================
__global__ __launch_bounds__(256) void k_colsum(const float* __restrict__ adj) {
    const int b  = blockIdx.z;
    const int j  = (blockIdx.x * 256 + threadIdx.x) * 4;
    const int i0 = blockIdx.y * (Nn / ISPLIT);
    const float4 dj = *(const float4*)(g_fdst + b * Nn + j);
    const float* __restrict__ fs = g_fsrc + b * Nn + i0;
    const float* __restrict__ ap = adj + ((size_t)b * Nn + i0) * Nn + j;

    float4 sum = make_float4(0.f, 0.f, 0.f, 0.f);
    #pragma unroll 16
    for (int i = 0; i < Nn / ISPLIT; ++i) {
        const float ci = fs[i];
        const float4 a = ldcs4(ap + (size_t)i * Nn);
        const float t0 = fmaf(C08L, a.x, ci + dj.x);
        const float t1 = fmaf(C08L, a.y, ci + dj.y);
        const float t2 = fmaf(C08L, a.z, ci + dj.z);
        const float t3 = fmaf(C08L, a.w, ci + dj.w);
        sum.x += (t0 > 0.f) ? ex2f(t0) : 0.f;
        sum.y += (t1 > 0.f) ? ex2f(t1) : 0.f;
        sum.z += (t2 > 0.f) ? ex2f(t2) : 0.f;
        sum.w += (t3 > 0.f) ? ex2f(t3) : 0.f;
    }
    *(float4*)(&g_part[blockIdx.y][b * Nn + j]) = sum;
}

// ============================================================================
// Kernel 3: reduce 64 partials; pack hs (tf32) + dj/fb pads into blobs.
// grid (64, Bc), 256 thr. Blob: 2 half-blobs x 128 segs x 20 floats;
// seg pad floats [16],[17] carry dj, fb for local j' = seg index (segs 0..31).
// ============================================================================
__global__ __launch_bounds__(256) void k_hpack() {
    __shared__ float sc[64];
    __shared__ float qsum[4][64];
    const int t = threadIdx.x;
    const int c = blockIdx.x;
    const int b = blockIdx.y;
    const int j0 = c * 64;

    {
        const int jl = t & 63;
        const int sl = t >> 6;           // slice 0..3 of 16 partials each
        float cs = 0.f;
        #pragma unroll
        for (int s = 0; s < ISPLIT / 4; ++s)
            cs += g_part[sl * (ISPLIT / 4) + s][b * Nn + j0 + jl];
        qsum[sl][jl] = cs;
    }
    __syncthreads();

    float* __restrict__ dst = g_hsC + (size_t)(b * 64 + c) * 5120;

    if (t < 64) {
        const float cs = qsum[0][t] + qsum[1][t] + qsum[2][t] + qsum[3][t];
        sc[t] = cs > 0.f ? (1.f / cs) : (1.f / (float)Nn);
        const int off = (t >> 5) * 2560 + (t & 31) * 20;
        dst[off + 16] = g_fdst[b * Nn + j0 + t];
        dst[off + 17] = cs > 0.f ? 0.f : 1.f;
    }
    __syncthreads();

    #pragma unroll
    for (int r = 0; r < 16; ++r) {
        const int o = t + r * 256;              // 0..4095
        const int s = o >> 4, i = o & 15;       // global seg 0..255
        const int ks = s >> 5;                  // kk group 0..7
        const int n07 = (s >> 2) & 7, k3 = s & 3;
        const int nt = i >> 1, h2 = i & 1;
        const int jl = ks * 8 + k3 + 4 * h2;    // j within chunk
        const int f  = nt * 8 + n07;
        const int halfidx = ks >> 2, kkloc = ks & 3;
        const float v = g_h[((size_t)(b * Nn) + j0 + jl) * 64 + f] * sc[jl];
        dst[halfidx * 2560 + (kkloc * 32 + (s & 31)) * 20 + i] =
            __uint_as_float(f2tf32(v));
    }
}

// ============================================================================
// Kernel 4 (hot): partial out = A_att @ hs via mma.sync tf32.
// 4-deep half-chunk pipeline. TI=128, 128 thr = 4 warps x 32 rows (2 m-tiles
// per warp -> B-fragment LDS redundancy halved). grid (32, Bc, 2), 2 CTAs/SM.
// ============================================================================
__device__ __forceinline__ void issue_half(uint32_t stg,
                                           const float* __restrict__ adjB,
                                           const float* __restrict__ hsCb,
                                           int hglob, int t) {
    // adj half tile: 128 rows x 32 cols, row stride 144B (1024 quads)
    const float* __restrict__ asrc = adjB + hglob * 32;
    #pragma unroll
    for (int q = 0; q < 8; ++q) {
        const int quad = t + q * 128;
        const int row = quad >> 3, c4 = quad & 7;
        CPA16(stg + (uint32_t)row * ADJ_ROW_B + (uint32_t)c4 * 16u,
              asrc + (size_t)row * Nn + c4 * 4);
    }
    // hs half blob: flat 2560 floats = 640 quads = 5 per thread
    const float* __restrict__ hsrc = hsCb + (size_t)hglob * 2560;
    const uint32_t hb = stg + ST_ADJ;
    #pragma unroll
    for (int q = 0; q < 5; ++q) {
        const int quad = t + q * 128;
        CPA16(hb + (uint32_t)quad * 16u, hsrc + quad * 4);
    }
}

__global__ __launch_bounds__(128, 2) void k_main(const float* __restrict__ adj) {
    extern __shared__ char dsm[];
    const uint32_t sm = smem_u32(dsm);

    const int t    = threadIdx.x;
    const int wid  = t >> 5;      // warp owns rows wid*32 .. wid*32+31
    const int lane = t & 31;
    const int lq   = lane >> 2;
    const int lm   = lane & 3;
    const int b    = blockIdx.y;
    const int i0   = blockIdx.x * TI;
    const int ks   = blockIdx.z;
    const int h0   = ks * NH;     // first global half index

    const float* __restrict__ adjB = adj + ((size_t)b * Nn + i0) * Nn;
    const float* __restrict__ hsCb = g_hsC + (size_t)b * 64 * 5120;

    // ci: rows i0 + wid*32 + mt*16 + sel*8 + lq
    float cil[4];
    #pragma unroll
    for (int k = 0; k < 4; ++k)
        cil[k] = g_fsrc[b * Nn + i0 + wid * 32 + (k >> 1) * 16 + (k & 1) * 8 + lq];

    float acc[2][8][4];
    #pragma unroll
    for (int mt = 0; mt < 2; ++mt)
        #pragma unroll
        for (int nt = 0; nt < 8; ++nt)
            #pragma unroll
            for (int q = 0; q < 4; ++q) acc[mt][nt][q] = 0.f;

    // prologue: halves 0,1,2 in flight
    #pragma unroll
    for (int p = 0; p < 3; ++p) {
        issue_half(sm + (uint32_t)p * STAGE, adjB, hsCb, h0 + p, t);
        asm volatile("cp.async.commit_group;" ::: "memory");
    }

    for (int h = 0; h < NH; ++h) {
        asm volatile("cp.async.wait_group 2;" ::: "memory");
        __syncthreads();   // data[h] visible; all warps done with stage (h-1)&3
        if (h + 3 < NH)
            issue_half(sm + (uint32_t)((h + 3) & 3) * STAGE, adjB, hsCb,
                       h0 + h + 3, t);
        asm volatile("cp.async.commit_group;" ::: "memory");

        const uint32_t stg  = sm + (uint32_t)(h & 3) * STAGE;
        const uint32_t hsb  = stg + ST_ADJ;
        const uint32_t adjW = stg + (uint32_t)(wid * 32) * ADJ_ROW_B;

        #pragma unroll
        for (int kkloc = 0; kkloc < 4; ++kkloc) {
            float dj0, fb0, dj4, fb4;
            {
                const uint32_t p0 = hsb + (uint32_t)(kkloc * 8 + lm) * 80u + 64u;
                const uint32_t p4 = hsb + (uint32_t)(kkloc * 8 + lm + 4) * 80u + 64u;
                asm volatile("ld.shared.v2.f32 {%0,%1}, [%2];"
                             : "=f"(dj0), "=f"(fb0) : "r"(p0));
                asm volatile("ld.shared.v2.f32 {%0,%1}, [%2];"
                             : "=f"(dj4), "=f"(fb4) : "r"(p4));
            }
            // B fragments: 4 x LDS.128, seg = kkloc*32 + lane (shared by 2 m-tiles)
            uint32_t bfr[16];
            #pragma unroll
            for (int v = 0; v < 4; ++v) {
                const uint32_t ba = hsb + (uint32_t)(kkloc * 32 + lane) * 80u
                                  + (uint32_t)v * 16u;
                asm volatile("ld.shared.v4.b32 {%0,%1,%2,%3}, [%4];"
                             : "=r"(bfr[v * 4]), "=r"(bfr[v * 4 + 1]),
                               "=r"(bfr[v * 4 + 2]), "=r"(bfr[v * 4 + 3])
                             : "r"(ba));
            }
            #pragma unroll
            for (int mt = 0; mt < 2; ++mt) {
                uint32_t au[4];
                #pragma unroll
                for (int kh = 0; kh < 2; ++kh) {
                    const float djv = kh ? dj4 : dj0;
                    const float fbv = kh ? fb4 : fb0;
                    #pragma unroll
                    for (int sel = 0; sel < 2; ++sel) {
                        float av;
                        const uint32_t aa = adjW
                            + (uint32_t)(mt * 16 + sel * 8 + lq) * ADJ_ROW_B
                            + (uint32_t)(kkloc * 8 + lm + 4 * kh) * 4u;
                        asm volatile("ld.shared.f32 %0, [%1];" : "=f"(av) : "r"(aa));
                        const float tl = fmaf(C08L, av, cil[mt * 2 + sel] + djv);
                        const float w  = tl > 0.f ? ex2f(tl) : fbv;
                        au[sel + 2 * kh] = f2tf32(w);
                    }
                }
                #pragma unroll
                for (int nt = 0; nt < 8; ++nt) {
                    const uint32_t b0 = bfr[(nt >> 1) * 4 + (nt & 1) * 2];
                    const uint32_t b1 = bfr[(nt >> 1) * 4 + (nt & 1) * 2 + 1];
                    MMA_TF32(acc[mt][nt], au, b0, b1);
                }
            }
        }
    }

    // epilogue: partial store
    float* __restrict__ pout = g_pout[ks] + ((size_t)(b * Nn) + i0 + wid * 32) * 64;
    #pragma unroll
    for (int mt = 0; mt < 2; ++mt) {
        #pragma unroll
        for (int nt = 0; nt < 8; ++nt) {
            const size_t base = (size_t)(mt * 16 + lq) * 64 + nt * 8 + 2 * lm;
            *(float2*)(pout + base)          = make_float2(acc[mt][nt][0], acc[mt][nt][1]);
            *(float2*)(pout + base + 8 * 64) = make_float2(acc[mt][nt][2], acc[mt][nt][3]);
        }
    }
}

// ============================================================================
// Kernel 5: out = relu(p0 + p1)
// ============================================================================
__global__ __launch_bounds__(256) void k_fin(float* __restrict__ out) {
    const int idx = (blockIdx.x * 256 + threadIdx.x) * 4;
    const float4 p0 = *(const float4*)(&g_pout[0][idx]);
    const float4 p1 = *(const float4*)(&g_pout[1][idx]);
    float4 r;
    r.x = fmaxf(p0.x + p1.x, 0.f);
    r.y = fmaxf(p0.y + p1.y, 0.f);
    r.z = fmaxf(p0.z + p1.z, 0.f);
    r.w = fmaxf(p0.w + p1.w, 0.f);
    *(float4*)(out + idx) = r;
}

// ============================================================================
extern "C" void kernel_launch(void* const* d_in, const int* in_sizes, int n_in,
                              void* d_out, int out_size) {
    const float *inp = nullptr, *adj = nullptr, *W = nullptr, *a = nullptr;
    for (int i = 0; i < n_in; ++i) {
        switch (in_sizes[i]) {
            case 1048576:  inp = (const float*)d_in[i]; break; // 4*4096*64
            case 67108864: adj = (const float*)d_in[i]; break; // 4*4096*4096
            case 4096:     W   = (const float*)d_in[i]; break; // 64*64
            case 128:      a   = (const float*)d_in[i]; break; // 128*1
            default: break;
        }
    }
    float* out = (float*)d_out;

    cudaFuncSetAttribute(k_main, cudaFuncAttributeMaxDynamicSharedMemorySize, SM_TOTAL);

    k_prep<<<Bc * Nn / 4, 256>>>(inp, W, a);

    dim3 g2(Nn / 1024, ISPLIT, Bc);
    k_colsum<<<g2, 256>>>(adj);

    dim3 g3(64, Bc);
    k_hpack<<<g3, 256>>>();

    dim3 g4(Nn / TI, Bc, KSPLIT);
    k_main<<<g4, 128, SM_TOTAL>>>(adj);

    k_fin<<<Bc * Nn * Ff / 1024, 256>>>(out);
}

// round 10
// speedup vs baseline: 1.3930x; 1.2582x over previous
#include <cuda_runtime.h>
#include <cuda_fp16.h>
#include <cstdint>

// Problem constants
#define Bc 4
#define Nn 4096
#define Ff 64
#define ISPLIT 64
#define TI 128
#define KSPLIT 4
#define NHC 32            // halves (32 j) per CTA in k_main
#define LOG2E 1.4426950408889634f
#define C08L  (0.8f * LOG2E)
#define SCALE_HS 1024.0f

// ---------------- scratch (device globals; no allocation allowed) ----------
__device__ float  g_h   [Bc * Nn * Ff];
__device__ __half g_p   [(size_t)Bc * Nn * Nn];     // exp weights, fp16 (134MB)
__device__ __half g_hsH [Bc * 128 * 2560];          // packed hs blobs (fp16)
__device__ float  g_fsrc[Bc * Nn];
__device__ float  g_fdst[Bc * Nn];
__device__ float  g_part[ISPLIT][Bc * Nn];
__device__ int    g_patchCnt;
__device__ int    g_patchList[Bc * Nn];
__device__ float  g_pout[KSPLIT][Bc * Nn * Ff];

// ---------------- helpers ---------------------------------------------------
__device__ __forceinline__ float ex2f(float x) {
    float r; asm("ex2.approx.f32 %0, %1;" : "=f"(r) : "f"(x)); return r;
}
__device__ __forceinline__ uint32_t smem_u32(const void* p) {
    uint32_t a;
    asm("{ .reg .u64 t; cvta.to.shared.u64 t, %1; cvt.u32.u64 %0, t; }" : "=r"(a) : "l"(p));
    return a;
}
__device__ __forceinline__ float4 ldcs4(const float* p) {
    float4 v;
    asm("ld.global.cs.v4.f32 {%0,%1,%2,%3}, [%4];"
        : "=f"(v.x), "=f"(v.y), "=f"(v.z), "=f"(v.w) : "l"(p));
    return v;
}
#define CPA16(dst, src) \
    asm volatile("cp.async.cg.shared.global [%0], [%1], 16;" :: "r"(dst), "l"(src))
#define MMA_F16(c, a, b0, b1) \
    asm volatile("mma.sync.aligned.m16n8k16.row.col.f32.f16.f16.f32 " \
        "{%0,%1,%2,%3},{%4,%5,%6,%7},{%8,%9},{%0,%1,%2,%3};" \
        : "+f"((c)[0]), "+f"((c)[1]), "+f"((c)[2]), "+f"((c)[3]) \
        : "r"((a)[0]), "r"((a)[1]), "r"((a)[2]), "r"((a)[3]), "r"(b0), "r"(b1))

// k_main smem: 4 stages of [p tile 128 rows x 80B | hs blob 64 segs x 80B]
#define ST_P    10240u
#define ST_HS   5120u
#define STAGE   (ST_P + ST_HS)       // 15360
#define SM_TOTAL (4u * STAGE)        // 61440 -> 3 CTAs/SM

// ============================================================================
// Kernel 1: h = inp @ W ; fsrc/fdst = 0.2*log2e * (lrelu(h) @ a halves)
// ============================================================================
__global__ __launch_bounds__(256) void k_prep(const float* __restrict__ inp,
                                              const float* __restrict__ W,
                                              const float* __restrict__ a) {
    __shared__ float Ws[64 * 64];
    __shared__ float as[128];
    __shared__ float inps[4][64];
    __shared__ float redS[4][2], redD[4][2];

    const int t = threadIdx.x;
    const int rowBase = blockIdx.x * 4;
    if (blockIdx.x == 0 && t == 0) g_patchCnt = 0;

    #pragma unroll
    for (int k = 0; k < 16; ++k) Ws[t + k * 256] = W[t + k * 256];
    if (t < 128) as[t] = a[t];

    const int r = t >> 6;
    const int o = t & 63;
    inps[r][o] = inp[(size_t)(rowBase + r) * 64 + o];
    __syncthreads();

    float hv = 0.f;
    #pragma unroll
    for (int f = 0; f < 64; ++f) hv = fmaf(inps[r][f], Ws[f * 64 + o], hv);

    const int gRow = rowBase + r;
    g_h[(size_t)gRow * 64 + o] = hv;

    const float lh = hv > 0.f ? hv : 0.2f * hv;
    float ps = lh * as[o];
    float pd = lh * as[64 + o];
    #pragma unroll
    for (int off = 16; off > 0; off >>= 1) {
        ps += __shfl_xor_sync(0xffffffffu, ps, off);
        pd += __shfl_xor_sync(0xffffffffu, pd, off);
    }
    const int wh = (t >> 5) & 1;
    if ((t & 31) == 0) { redS[r][wh] = ps; redD[r][wh] = pd; }
    __syncthreads();
    if ((t & 63) == 0) {
        g_fsrc[gRow] = 0.2f * LOG2E * (redS[r][0] + redS[r][1]);
        g_fdst[gRow] = 0.2f * LOG2E * (redD[r][0] + redD[r][1]);
    }
}

// ============================================================================
// Kernel 2: k_expsum — exp ONCE: p = (t>0 ? 2^t : 0) stored fp16; colsum
// partials accumulated. grid (2, 64, Bc), 256 thr, 8 j per thread.
// ============================================================================
__global__ __launch_bounds__(256) void k_expsum(const float* __restrict__ adj) {
    const int b  = blockIdx.z;
    const int j8 = (blockIdx.x * 256 + threadIdx.x) * 8;
    const int i0 = blockIdx.y * (Nn / ISPLIT);
    const float4 djA = *(const float4*)(g_fdst + b * Nn + j8);
    const float4 djB = *(const float4*)(g_fdst + b * Nn + j8 + 4);
    const float* __restrict__ fs = g_fsrc + b * Nn + i0;
    const float* __restrict__ ap = adj + ((size_t)b * Nn + i0) * Nn + j8;
    __half* __restrict__ pp = g_p + ((size_t)(b * Nn + i0)) * Nn + j8;

    float4 sA = make_float4(0.f, 0.f, 0.f, 0.f);
    float4 sB = make_float4(0.f, 0.f, 0.f, 0.f);
    #pragma unroll 4
    for (int r = 0; r < Nn / ISPLIT; ++r) {
        const float ci = fs[r];
        const float4 a0 = ldcs4(ap + (size_t)r * Nn);
        const float4 a1 = ldcs4(ap + (size_t)r * Nn + 4);
        float e0 = 0.f, e1 = 0.f, e2 = 0.f, e3 = 0.f;
        float e4 = 0.f, e5 = 0.f, e6 = 0.f, e7 = 0.f;
        {
            const float t0 = fmaf(C08L, a0.x, ci + djA.x);
            const float t1 = fmaf(C08L, a0.y, ci + djA.y);
            const float t2 = fmaf(C08L, a0.z, ci + djA.z);
            const float t3 = fmaf(C08L, a0.w, ci + djA.w);
            const float t4 = fmaf(C08L, a1.x, ci + djB.x);
            const float t5 = fmaf(C08L, a1.y, ci + djB.y);
            const float t6 = fmaf(C08L, a1.z, ci + djB.z);
            const float t7 = fmaf(C08L, a1.w, ci + djB.w);
            if (t0 > 0.f) e0 = ex2f(t0);
            if (t1 > 0.f) e1 = ex2f(t1);
            if (t2 > 0.f) e2 = ex2f(t2);
            if (t3 > 0.f) e3 = ex2f(t3);
            if (t4 > 0.f) e4 = ex2f(t4);
            if (t5 > 0.f) e5 = ex2f(t5);
            if (t6 > 0.f) e6 = ex2f(t6);
            if (t7 > 0.f) e7 = ex2f(t7);
        }
        sA.x += e0; sA.y += e1; sA.z += e2; sA.w += e3;
        sB.x += e4; sB.y += e5; sB.z += e6; sB.w += e7;
        __half2 h0 = __floats2half2_rn(e0, e1);
        __half2 h1 = __floats2half2_rn(e2, e3);
        __half2 h2 = __floats2half2_rn(e4, e5);
        __half2 h3 = __floats2half2_rn(e6, e7);
        uint4 w;
        w.x = *reinterpret_cast<uint32_t*>(&h0);
        w.y = *reinterpret_cast<uint32_t*>(&h1);
        w.z = *reinterpret_cast<uint32_t*>(&h2);
        w.w = *reinterpret_cast<uint32_t*>(&h3);
        *reinterpret_cast<uint4*>(pp + (size_t)r * Nn) = w;
    }
    *(float4*)(&g_part[blockIdx.y][b * Nn + j8])     = sA;
    *(float4*)(&g_part[blockIdx.y][b * Nn + j8 + 4]) = sB;
}

// ============================================================================
// Kernel 3: reduce partials; pack hs*1024/colsum (fp16) into B-frag blobs.
// grid (64 chunks, Bc). Seg layout per half: seg = ks2*32+lane (80B each);
// seg content: [nt=0..7] x {b0,b1,b2,b3}.
// ============================================================================
__global__ __launch_bounds__(256) void k_hpack() {
    __shared__ float sc[64];
    __shared__ float qsum[4][64];
    const int t = threadIdx.x;
    const int c = blockIdx.x;
    const int b = blockIdx.y;
    const int j0 = c * 64;

    {
        const int jl = t & 63;
        const int sl = t >> 6;
        float cs = 0.f;
        #pragma unroll
        for (int s = 0; s < ISPLIT / 4; ++s)
            cs += g_part[sl * (ISPLIT / 4) + s][b * Nn + j0 + jl];
        qsum[sl][jl] = cs;
    }
    __syncthreads();
    if (t < 64) {
        const float cs = qsum[0][t] + qsum[1][t] + qsum[2][t] + qsum[3][t];
        sc[t] = cs > 0.f ? (SCALE_HS / cs) : (SCALE_HS / (float)Nn);
        if (!(cs > 0.f)) {
            const int idx = atomicAdd(&g_patchCnt, 1);
            g_patchList[idx] = b * Nn + j0 + t;
        }
    }
    __syncthreads();

    __half* __restrict__ dstBase = g_hsH + (size_t)(b * 128 + c * 2) * 2560;
    #pragma unroll
    for (int r = 0; r < 16; ++r) {
        const int o = t + r * 256;              // 0..4095
        const int hh2 = o >> 11;
        const int rem = o & 2047;
        const int seg = rem >> 5, pos = rem & 31;
        const int ks2 = seg >> 5, lane = seg & 31;
        const int lq = lane >> 2, lm = lane & 3;
        const int nt = pos >> 2, q = pos & 3;
        const int jl = hh2 * 32 + ks2 * 16 + 2 * lm + (q & 1) + (q >> 1) * 8;
        const int f  = nt * 8 + lq;
        const float v = g_h[((size_t)(b * Nn) + j0 + jl) * 64 + f] * sc[jl];
        dstBase[(size_t)hh2 * 2560 + seg * 40 + pos] = __float2half_rn(v);
    }
}

// ============================================================================
// Kernel 3b: patch degenerate columns (colsum==0): p[:, j] = 1.0h.
// Normally g_patchCnt == 0 -> immediate exit.
// ============================================================================
__global__ __launch_bounds__(256) void k_patch() {
    const int n = g_patchCnt;
    const int t = blockIdx.x * 256 + threadIdx.x;
    for (int l = 0; l < n; ++l) {
        const int col = g_patchList[l];
        const int bb = col >> 12, j = col & (Nn - 1);
        for (int i = t; i < Nn; i += 16 * 256)
            g_p[((size_t)(bb * Nn) + i) * Nn + j] = __ushort_as_half(0x3C00);
    }
}

// ============================================================================
// Kernel 4 (hot): pure fp16 GEMM out' = P @ hs' via mma.m16n8k16.
// 4-deep half pipeline, 128 thr = 4 warps x 32 rows. grid (32, Bc, 4).
// 3 CTAs/SM.
// ============================================================================
__device__ __forceinline__ void issue_half(uint32_t stg,
                                           const __half* __restrict__ pB,
                                           const __half* __restrict__ hsHb,
                                           int hglob, int t) {
    // p tile: 128 rows x 64B data, dst row stride 80B
    const __half* __restrict__ psrc = pB + hglob * 32;
    #pragma unroll
    for (int q = 0; q < 4; ++q) {
        const int quad = t + q * 128;
        const int row = quad >> 2, c4 = quad & 3;
        CPA16(stg + (uint32_t)row * 80u + (uint32_t)c4 * 16u,
              psrc + (size_t)row * Nn + c4 * 8);
    }
    // hs blob: flat 5120B = 320 quads
    const __half* __restrict__ hsrc = hsHb + (size_t)hglob * 2560;
    const uint32_t hb = stg + ST_P;
    CPA16(hb + (uint32_t)t * 16u, hsrc + t * 8);
    CPA16(hb + (uint32_t)(t + 128) * 16u, hsrc + (t + 128) * 8);
    if (t < 64)
        CPA16(hb + (uint32_t)(t + 256) * 16u, hsrc + (t + 256) * 8);
}

__global__ __launch_bounds__(128, 3) void k_main() {
    extern __shared__ char dsm[];
    const uint32_t sm = smem_u32(dsm);

    const int t    = threadIdx.x;
    const int wid  = t >> 5;
    const int lane = t & 31;
    const int lq   = lane >> 2;
    const int lm   = lane & 3;
    const int b    = blockIdx.y;
    const int i0   = blockIdx.x * TI;
    const int ks   = blockIdx.z;
    const int h0   = ks * NHC;

    const __half* __restrict__ pB   = g_p + ((size_t)(b * Nn + i0)) * Nn;
    const __half* __restrict__ hsHb = g_hsH + (size_t)b * 128 * 2560;

    float acc[2][8][4];
    #pragma unroll
    for (int mt = 0; mt < 2; ++mt)
        #pragma unroll
        for (int nt = 0; nt < 8; ++nt)
            #pragma unroll
            for (int q = 0; q < 4; ++q) acc[mt][nt][q] = 0.f;

    #pragma unroll
    for (int p = 0; p < 3; ++p) {
        issue_half(sm + (uint32_t)p * STAGE, pB, hsHb, h0 + p, t);
        asm volatile("cp.async.commit_group;" ::: "memory");
    }

    for (int h = 0; h < NHC; ++h) {
        asm volatile("cp.async.wait_group 2;" ::: "memory");
        __syncthreads();
        if (h + 3 < NHC)
            issue_half(sm + (uint32_t)((h + 3) & 3) * STAGE, pB, hsHb,
                       h0 + h + 3, t);
        asm volatile("cp.async.commit_group;" ::: "memory");

        const uint32_t stg = sm + (uint32_t)(h & 3) * STAGE;
        const uint32_t hsb = stg + ST_P;

        #pragma unroll
        for (int ks2 = 0; ks2 < 2; ++ks2) {
            // B fragments: 4 x LDS.128 from seg (ks2*32 + lane)
            uint32_t bfr[16];
            #pragma unroll
            for (int v = 0; v < 4; ++v) {
                const uint32_t ba = hsb + (uint32_t)(ks2 * 32 + lane) * 80u
                                  + (uint32_t)v * 16u;
                asm volatile("ld.shared.v4.b32 {%0,%1,%2,%3}, [%4];"
                             : "=r"(bfr[v * 4]), "=r"(bfr[v * 4 + 1]),
                               "=r"(bfr[v * 4 + 2]), "=r"(bfr[v * 4 + 3])
                             : "r"(ba));
            }
            // A fragments per m-tile: 4 x LDS.32
            uint32_t au[2][4];
            #pragma unroll
            for (int mt = 0; mt < 2; ++mt) {
                const uint32_t base = stg
                    + (uint32_t)(wid * 32 + mt * 16 + lq) * 80u
                    + (uint32_t)(ks2 * 32 + lm * 4);
                asm volatile("ld.shared.b32 %0, [%1];" : "=r"(au[mt][0]) : "r"(base));
                asm volatile("ld.shared.b32 %0, [%1];" : "=r"(au[mt][1]) : "r"(base + 640u));
                asm volatile("ld.shared.b32 %0, [%1];" : "=r"(au[mt][2]) : "r"(base + 16u));
                asm volatile("ld.shared.b32 %0, [%1];" : "=r"(au[mt][3]) : "r"(base + 656u));
            }
            #pragma unroll
            for (int mt = 0; mt < 2; ++mt)
                #pragma unroll
                for (int nt = 0; nt < 8; ++nt) {
                    const uint32_t b0 = bfr[(nt >> 1) * 4 + (nt & 1) * 2];
                    const uint32_t b1 = bfr[(nt >> 1) * 4 + (nt & 1) * 2 + 1];
                    MMA_F16(acc[mt][nt], au[mt], b0, b1);
                }
        }
    }

    // epilogue: undo SCALE_HS; store partials
    float* __restrict__ pout = g_pout[ks] + ((size_t)(b * Nn) + i0 + wid * 32) * 64;
    const float inv = 1.0f / SCALE_HS;
    #pragma unroll
    for (int mt = 0; mt < 2; ++mt) {
        #pragma unroll
        for (int nt = 0; nt < 8; ++nt) {
            const size_t base = (size_t)(mt * 16 + lq) * 64 + nt * 8 + 2 * lm;
            *(float2*)(pout + base) =
                make_float2(acc[mt][nt][0] * inv, acc[mt][nt][1] * inv);
            *(float2*)(pout + base + 8 * 64) =
                make_float2(acc[mt][nt][2] * inv, acc[mt][nt][3] * inv);
        }
    }
}

// ============================================================================
// Kernel 5: out = relu(sum of 4 partials)
// ============================================================================
__global__ __launch_bounds__(256) void k_fin(float* __restrict__ out) {
    const int idx = (blockIdx.x * 256 + threadIdx.x) * 4;
    float4 r = *(const float4*)(&g_pout[0][idx]);
    #pragma unroll
    for (int s = 1; s < KSPLIT; ++s) {
        const float4 p = *(const float4*)(&g_pout[s][idx]);
        r.x += p.x; r.y += p.y; r.z += p.z; r.w += p.w;
    }
    r.x = fmaxf(r.x, 0.f);
    r.y = fmaxf(r.y, 0.f);
    r.z = fmaxf(r.z, 0.f);
    r.w = fmaxf(r.w, 0.f);
    *(float4*)(out + idx) = r;
}

// ============================================================================
extern "C" void kernel_launch(void* const* d_in, const int* in_sizes, int n_in,
                              void* d_out, int out_size) {
    const float *inp = nullptr, *adj = nullptr, *W = nullptr, *a = nullptr;
    for (int i = 0; i < n_in; ++i) {
        switch (in_sizes[i]) {
            case 1048576:  inp = (const float*)d_in[i]; break; // 4*4096*64
            case 67108864: adj = (const float*)d_in[i]; break; // 4*4096*4096
            case 4096:     W   = (const float*)d_in[i]; break; // 64*64
            case 128:      a   = (const float*)d_in[i]; break; // 128*1
            default: break;
        }
    }
    float* out = (float*)d_out;

    cudaFuncSetAttribute(k_main, cudaFuncAttributeMaxDynamicSharedMemorySize, SM_TOTAL);

    k_prep<<<Bc * Nn / 4, 256>>>(inp, W, a);

    dim3 g2(Nn / 2048, ISPLIT, Bc);
    k_expsum<<<g2, 256>>>(adj);

    dim3 g3(64, Bc);
    k_hpack<<<g3, 256>>>();

    k_patch<<<16, 256>>>();

    dim3 g4(Nn / TI, Bc, KSPLIT);
    k_main<<<g4, 128, SM_TOTAL>>>();

    k_fin<<<Bc * Nn * Ff / 1024, 256>>>(out);
}